// round 8
// baseline (speedup 1.0000x reference)
#include <cuda_runtime.h>
#include <cuda_bf16.h>
#include <math.h>

#define IH 1024
#define IW 1024
#define NB 8
#define CH (IH * IW)
#define SPAN 26   // output columns per warp (lanes 3..28)
#define RB 32     // output rows per warp

// tan((2k+1)*pi/16)
#define T0 0.1989123673796580f
#define T1 0.6681786379192989f
#define T2 1.4966057626654890f
#define T3 5.0273394921258481f
#define INV3 0.3333333333333333f

__device__ __forceinline__ int quant_q(float sx, float sy) {
    float ax = fabsf(sx), ay = fabsf(sy);
    int mm = (int)(ay > T0 * ax) + (int)(ay > T1 * ax)
           + (int)(ay > T2 * ax) + (int)(ay > T3 * ax);
    int neg = (__float_as_int(sx) ^ __float_as_int(sy)) < 0;
    return neg ? 4 - mm : 4 + mm;
}

// NMS: rows g0*=above, g1*=center(l/r), g2*=below; center value gmc
__device__ __forceinline__ float nms_t(int k, float gmc,
                                       float g00, float g01, float g02,
                                       float g10,            float g12,
                                       float g20, float g21, float g22) {
    float mx0 = fmaxf(g10, g12);   // k=0: (0,±1)
    float mx1 = fmaxf(g02, g20);   // k=1: (-1,1)/(1,-1)
    float mx2 = fmaxf(g01, g21);   // k=2: (±1,0)
    float mx3 = fmaxf(g00, g22);   // k=3: (-1,-1)/(1,1)
    float mxa = (k & 1) ? mx1 : mx0;
    float mxb = (k & 1) ? mx3 : mx2;
    float mx  = (k & 2) ? mxb : mxa;
    float thin = (gmc > mx) ? gmc : 0.0f;
    return (thin > 0.5f ? 0.5f : 0.0f) + (thin > 1.0f ? 0.5f : 0.0f);
}

__global__ __launch_bounds__(256)
void canny_warp_kernel(const float* __restrict__ img, float* __restrict__ out)
{
    const int lane  = threadIdx.x & 31;
    const int warp  = threadIdx.x >> 5;
    const int strip = blockIdx.x;                    // 0..39
    const int b     = blockIdx.z;
    const int R0    = (blockIdx.y * 8 + warp) * RB;  // output rows [R0, R0+RB)
    const int ic    = strip * SPAN - 3 + lane;       // this lane's image column
    const bool colOK   = (unsigned)ic < IW;
    const bool outLane = (lane >= 3) && (lane <= 28) && (ic < IW);

    const float* imgb = img + (size_t)b * 3 * CH;
    const size_t plane = (size_t)NB * CH;
    float* o_gx = out;
    float* o_gy = out + plane;
    float* o_gm = out + 2 * plane;
    float* o_or = out + 3 * plane;
    float* o_te = out + 4 * plane;

    // rolling pipeline state (suffix 1 = one row older, 2 = two rows older)
    float u1 = 0, u2 = 0, v1 = 0, v2 = 0;             // horizontal sobel partials
    float sx1 = 0, sy1 = 0, sx2 = 0, sy2 = 0;         // gradients
    float gl1 = 0, gc1 = 0, gr1 = 0;                  // gm (left/center/right)
    float gl2 = 0, gc2 = 0, gr2 = 0;
    float t1 = 0, rs1 = 0, rs2 = 0;                   // thin-edge & 3-tap row sums

    #pragma unroll 2
    for (int i = 0; i < RB + 6; i++) {
        int gy = R0 - 3 + i;

        // load channel-summed pixel (SAME zero padding)
        float s = 0.0f;
        if (colOK && (unsigned)gy < IH) {
            const float* p = imgb + (size_t)gy * IW + ic;
            s = p[0] + p[CH] + p[2 * CH];
        }
        float sl = __shfl_up_sync(0xffffffffu, s, 1);
        float sr = __shfl_down_sync(0xffffffffu, s, 1);
        float u0 = sr - sl;
        float v0 = 0.5f * (sl + sr) + s;

        // sobel centered at row gy-1 (canonical u/v composition, bit-identical to R7)
        float sxn = (0.5f * (u2 + u0) + u1) * INV3;
        float syn = (v0 - v2) * INV3;
        float gmn = sqrtf(sxn * sxn + syn * syn);
        if (!colOK || (unsigned)(gy - 1) >= IH) gmn = 0.0f;   // gm zero outside image
        float gln = __shfl_up_sync(0xffffffffu, gmn, 1);
        float grn = __shfl_down_sync(0xffffffffu, gmn, 1);

        // NMS + thresholds at row gy-2 (gm rows gy-3..gy-1; sx,sy at gy-2)
        int k = quant_q(sx1, sy1) & 3;
        float tn = nms_t(k, gc1, gl2, gc2, gr2, gl1, gr1, gln, gmn, grn);
        if (!colOK || (unsigned)(gy - 2) >= IH) tn = 0.0f;    // t zero outside image
        float tl = __shfl_up_sync(0xffffffffu, tn, 1);
        float tr = __shfl_down_sync(0xffffffffu, tn, 1);
        float rsn = tl + tn + tr;

        // hysteresis + all 5 planes at row Y = gy-3
        if (i >= 6 && outLane) {
            int Y = gy - 3;
            float sum = rs2 + rs1 + rsn;          // t rows Y-1, Y, Y+1 (exact halves)
            int q = quant_q(sx2, sy2);
            float qv = (float)q * 45.0f;
            if (sx2 == 0.0f && sy2 == 0.0f) qv = __int_as_float(0x7fc00000);
            float high = (t1 == 1.0f) ? 1.0f : 0.0f;
            float weak = ((sum * 1.25f > 1.0f) && (t1 == 0.5f)) ? 1.0f : 0.0f;
            size_t o = (size_t)b * CH + (size_t)Y * IW + (unsigned)ic;
            __stcs(o_gx + o, sx2);
            __stcs(o_gy + o, sy2);
            __stcs(o_gm + o, gc2);
            __stcs(o_or + o, qv);
            __stcs(o_te + o, high + weak);
        }

        // roll
        u2 = u1; u1 = u0; v2 = v1; v1 = v0;
        sx2 = sx1; sy2 = sy1; sx1 = sxn; sy1 = syn;
        gl2 = gl1; gc2 = gc1; gr2 = gr1;
        gl1 = gln; gc1 = gmn; gr1 = grn;
        t1 = tn; rs2 = rs1; rs1 = rsn;
    }
}

extern "C" void kernel_launch(void* const* d_in, const int* in_sizes, int n_in,
                              void* d_out, int out_size)
{
    const float* img = (const float*)d_in[0];
    float* out = (float*)d_out;
    dim3 block(256, 1, 1);
    dim3 grid((IW + SPAN - 1) / SPAN,      // 40 column strips
              IH / (8 * RB),               // 4 row-band groups (8 warps each)
              NB);
    canny_warp_kernel<<<grid, block>>>(img, out);
}

// round 9
// speedup vs baseline: 1.2879x; 1.2879x over previous
#include <cuda_runtime.h>
#include <cuda_bf16.h>
#include <math.h>

#define IH 1024
#define IW 1024
#define NB 8
#define TW 32
#define TH 64
#define SIW 40   // s_img row stride; col c <-> gx = x0-4+c, row r <-> gy = y0-3+r
#define SW  36   // s_gm / s_t row stride

// tan((2k+1)*pi/16)
#define T0 0.1989123673796580f
#define T1 0.6681786379192989f
#define T2 1.4966057626654890f
#define T3 5.0273394921258481f
#define INV3 0.3333333333333333f

__device__ __forceinline__ int quant_q(float sx, float sy) {
    float ax = fabsf(sx), ay = fabsf(sy);
    int mm = (int)(ay > T0 * ax) + (int)(ay > T1 * ax)
           + (int)(ay > T2 * ax) + (int)(ay > T3 * ax);
    int neg = (__float_as_int(sx) ^ __float_as_int(sy)) < 0;
    return neg ? 4 - mm : 4 + mm;
}

// sobel at gm-coord (R,C): taps s_img rows R..R+2, cols C+1..C+3 (canonical u/v form)
__device__ __forceinline__ void sobel_at(const float* __restrict__ s_img, int R, int C,
                                         float& sx, float& sy) {
    const float* ip = s_img + R * SIW + (C + 1);
    float a0 = ip[0],       a1 = ip[1],           a2 = ip[2];
    float b0 = ip[SIW],                           b2 = ip[SIW + 2];
    float c0 = ip[2 * SIW], c1 = ip[2 * SIW + 1], c2 = ip[2 * SIW + 2];
    float u0 = a2 - a0, v0 = 0.5f * (a0 + a2) + a1;
    float u1 = b2 - b0;
    float u2 = c2 - c0, v2 = 0.5f * (c0 + c2) + c1;
    sx = (0.5f * (u0 + u2) + u1) * INV3;
    sy = (v2 - v0) * INV3;
}

__device__ __forceinline__ float nms_t(int k, float gmc,
                                       float g00, float g01, float g02,
                                       float g10,            float g12,
                                       float g20, float g21, float g22) {
    float mx0 = fmaxf(g10, g12);   // k=0: (0,±1)
    float mx1 = fmaxf(g02, g20);   // k=1: (-1,1)/(1,-1)
    float mx2 = fmaxf(g01, g21);   // k=2: (±1,0)
    float mx3 = fmaxf(g00, g22);   // k=3: (-1,-1)/(1,1)
    float mxa = (k & 1) ? mx1 : mx0;
    float mxb = (k & 1) ? mx3 : mx2;
    float mx  = (k & 2) ? mxb : mxa;
    float thin = (gmc > mx) ? gmc : 0.0f;
    return (thin > 0.5f ? 0.5f : 0.0f) + (thin > 1.0f ? 0.5f : 0.0f);
}

template<bool EDGE>
__device__ __forceinline__ void body(
    const float* __restrict__ imgb, float* __restrict__ out,
    int b, int x0, int y0, int tx, int ty, int tid,
    float* __restrict__ s_img, float* __restrict__ s_gm, float* __restrict__ s_t)
{
    // ---- P1: channel-summed image, rows 0..69 (gy=y0-3+r) x cols 0..39 (gx=x0-4+c)
    if (!EDGE) {
        const float4* base = (const float4*)(imgb + (size_t)(y0 - 3) * IW + (x0 - 4));
        const int CH4 = IH * IW / 4;
        #pragma unroll
        for (int p = 0; p < 3; p++) {
            int idx = tid + 256 * p;
            if (idx < 700) {
                int r = idx / 10, c4 = idx % 10;
                const float4* ptr = base + r * (IW / 4) + c4;
                float4 v0 = ptr[0], v1 = ptr[CH4], v2 = ptr[2 * CH4];
                float4 s;
                s.x = v0.x + v1.x + v2.x; s.y = v0.y + v1.y + v2.y;
                s.z = v0.z + v1.z + v2.z; s.w = v0.w + v1.w + v2.w;
                *(float4*)&s_img[r * SIW + c4 * 4] = s;
            }
        }
    } else {
        #pragma unroll
        for (int p = 0; p < 11; p++) {
            int idx = tid + 256 * p;
            if (idx < 2800) {
                int r = idx / 40, c = idx % 40;
                int gy = y0 - 3 + r, gx = x0 - 4 + c;
                float v = 0.0f;
                if ((unsigned)gy < IH && (unsigned)gx < IW) {
                    size_t o = (size_t)gy * IW + gx;
                    v = imgb[o] + imgb[o + IH * IW] + imgb[o + 2 * IH * IW];
                }
                s_img[r * SIW + c] = v;
            }
        }
    }
    __syncthreads();

    // ---- P2: gm only. row r <-> gy=y0-2+r (0..67), col c <-> gx=x0-2+c (0..35)
    auto p2_at = [&](int r, int c) {
        float sx, sy;
        sobel_at(s_img, r, c, sx, sy);
        float gm = sqrtf(sx * sx + sy * sy);
        if (EDGE) {
            int gy = y0 - 2 + r, gx = x0 - 2 + c;
            if (!((unsigned)gy < IH && (unsigned)gx < IW)) gm = 0.f;
        }
        s_gm[r * SW + c] = gm;
    };
    {   // main rolling: rows 2..65, col tx
        int r0 = 2 + 8 * ty, c = tx;
        const float* ip = s_img + r0 * SIW + (c + 1);
        float a0 = ip[0], a1 = ip[1], a2 = ip[2];
        float u0 = a2 - a0, v0 = 0.5f * (a0 + a2) + a1;
        float b0 = ip[SIW], b1 = ip[SIW + 1], b2 = ip[SIW + 2];
        float u1 = b2 - b0, v1 = 0.5f * (b0 + b2) + b1;
        #pragma unroll
        for (int j = 0; j < 8; j++) {
            const float* rp = ip + (j + 2) * SIW;
            float c0 = rp[0], c1 = rp[1], c2 = rp[2];
            float u2 = c2 - c0, v2 = 0.5f * (c0 + c2) + c1;
            float sx = (0.5f * (u0 + u2) + u1) * INV3;
            float sy = (v2 - v0) * INV3;
            float gm = sqrtf(sx * sx + sy * sy);
            int r = r0 + j;
            if (EDGE) {
                int gy = y0 - 2 + r, gx = x0 - 2 + c;
                if (!((unsigned)gy < IH && (unsigned)gx < IW)) gm = 0.f;
            }
            s_gm[r * SW + c] = gm;
            u0 = u1; u1 = u2; v0 = v1; v1 = v2;
        }
    }
    if (tid < 144) {            // tail A: rows {0,1,66,67} x cols 0..35
        int rr = tid / 36, c = tid % 36;
        p2_at((rr < 2) ? rr : 64 + rr, c);
    }
    {                           // tail B: rows 2..65 x cols 32..35 (exactly 256)
        p2_at(2 + (tid >> 2), 32 + (tid & 3));
    }
    __syncthreads();

    // ---- P3: quant + NMS -> t; ALSO writes gx/gy/gm/orient planes.
    // t row r <-> gy=y0-1+r (0..65), col c <-> gx=x0-1+c (0..33).
    // Main maps c = tx+1 (cols 1..32): pixel == output pixel (always in-image).
    const size_t plane = (size_t)NB * IH * IW;
    float* o_gx = out;
    float* o_gy = out + plane;
    float* o_gm = out + 2 * plane;
    float* o_or = out + 3 * plane;
    float* o_te = out + 4 * plane;

    auto p3_halo = [&](int r, int c) {   // halo t only, no gmem write
        float sx, sy;
        sobel_at(s_img, r + 1, c + 1, sx, sy);
        const float* gp = s_gm + r * SW + c;
        float gmc = gp[SW + 1];
        int k = quant_q(sx, sy) & 3;
        float t = nms_t(k, gmc, gp[0], gp[1], gp[2], gp[SW], gp[SW + 2],
                        gp[2 * SW], gp[2 * SW + 1], gp[2 * SW + 2]);
        if (EDGE) {
            int gy = y0 - 1 + r, gx = x0 - 1 + c;
            if (!((unsigned)gy < IH && (unsigned)gx < IW)) t = 0.0f;
        }
        s_t[r * SW + c] = t;
    };
    {   // main rolling: rows 1..64, col c = tx+1. No EDGE guard needed (pixels in-image).
        int r0 = 1 + 8 * ty, c = tx + 1;
        const float* gp = s_gm + r0 * SW + c;
        float gA0 = gp[0],  gA1 = gp[1],      gA2 = gp[2];
        float gB0 = gp[SW], gB1 = gp[SW + 1], gB2 = gp[SW + 2];
        // img rolling for sobel at gm-coord (r+1, c+1): rows r+1..r+3, cols c+2..c+4
        const float* ip = s_img + (r0 + 1) * SIW + (c + 2);
        float a0 = ip[0], a1 = ip[1], a2 = ip[2];
        float u0 = a2 - a0, v0 = 0.5f * (a0 + a2) + a1;
        float b0 = ip[SIW], b1 = ip[SIW + 1], b2 = ip[SIW + 2];
        float u1 = b2 - b0, v1 = 0.5f * (b0 + b2) + b1;
        size_t obase = (size_t)b * IH * IW + (size_t)(y0 + 8 * ty) * IW + (x0 + tx);
        #pragma unroll
        for (int j = 0; j < 8; j++) {
            int r = r0 + j;
            const float* gq = s_gm + (r + 2) * SW + c;
            float gC0 = gq[0], gC1 = gq[1], gC2 = gq[2];
            const float* rp = ip + (j + 2) * SIW;
            float c0 = rp[0], c1 = rp[1], c2 = rp[2];
            float u2 = c2 - c0, v2 = 0.5f * (c0 + c2) + c1;
            float sx = (0.5f * (u0 + u2) + u1) * INV3;
            float sy = (v2 - v0) * INV3;
            int q = quant_q(sx, sy);
            float t = nms_t(q & 3, gB1, gA0, gA1, gA2, gB0, gB2, gC0, gC1, gC2);
            s_t[r * SW + c] = t;
            // neighbor-independent output planes for pixel (y0+8ty+j, x0+tx)
            float qv = (float)q * 45.0f;
            if (sx == 0.0f && sy == 0.0f) qv = __int_as_float(0x7fc00000);
            size_t o = obase + (size_t)j * IW;
            __stcs(o_gx + o, sx);
            __stcs(o_gy + o, sy);
            __stcs(o_gm + o, gB1);
            __stcs(o_or + o, qv);
            gA0 = gB0; gA1 = gB1; gA2 = gB2;
            gB0 = gC0; gB1 = gC1; gB2 = gC2;
            u0 = u1; u1 = u2; v0 = v1; v1 = v2;
        }
    }
    if (tid < 68) {             // tail A: rows {0,65} x cols 0..33
        int rr = tid / 34, c = tid % 34;
        p3_halo(rr ? 65 : 0, c);
    } else if (tid < 196) {     // tail B: rows 1..64 x cols {0,33}
        int k2 = tid - 68;
        p3_halo(1 + (k2 >> 1), (k2 & 1) ? 33 : 0);
    }
    __syncthreads();

    // ---- P4: thin-edges plane only (hysteresis). Output rows 8ty..8ty+7, col tx.
    {
        int r0 = 8 * ty, ix = tx;
        const float* tp = s_t + r0 * SW + ix;
        float rs0 = tp[0]  + tp[1]      + tp[2];
        float rs1 = tp[SW] + tp[SW + 1] + tp[SW + 2];
        size_t obase = (size_t)b * IH * IW + (size_t)(y0 + r0) * IW + (x0 + ix);
        #pragma unroll
        for (int j = 0; j < 8; j++) {
            const float* rp = tp + (j + 2) * SW;
            float rs2 = rp[0] + rp[1] + rp[2];
            float sum = rs0 + rs1 + rs2;
            float tc = tp[(j + 1) * SW + 1];
            float high = (tc == 1.0f) ? 1.0f : 0.0f;
            float weak = ((sum * 1.25f > 1.0f) && (tc == 0.5f)) ? 1.0f : 0.0f;
            __stcs(o_te + obase + (size_t)j * IW, high + weak);
            rs0 = rs1; rs1 = rs2;
        }
    }
}

__global__ __launch_bounds__(256, 6)
void canny_fused_kernel(const float* __restrict__ img, float* __restrict__ out)
{
    __shared__ float s_img[70 * SIW];        // 2800 floats
    __shared__ float s_gm [68 * SW + 8];     // 2456
    __shared__ float s_t  [66 * SW + 8];     // 2384   (total ~30.6 KB)

    const int b  = blockIdx.z;
    const int x0 = blockIdx.x * TW;
    const int y0 = blockIdx.y * TH;
    const int tx = threadIdx.x;
    const int ty = threadIdx.y;
    const int tid = ty * 32 + tx;

    const float* imgb = img + (size_t)b * 3 * IH * IW;

    const bool edge = (x0 == 0) || (y0 == 0) || (x0 + TW == IW) || (y0 + TH == IH);
    if (edge)
        body<true >(imgb, out, b, x0, y0, tx, ty, tid, s_img, s_gm, s_t);
    else
        body<false>(imgb, out, b, x0, y0, tx, ty, tid, s_img, s_gm, s_t);
}

extern "C" void kernel_launch(void* const* d_in, const int* in_sizes, int n_in,
                              void* d_out, int out_size)
{
    const float* img = (const float*)d_in[0];
    float* out = (float*)d_out;
    dim3 block(32, 8, 1);
    dim3 grid(IW / TW, IH / TH, NB);
    canny_fused_kernel<<<grid, block>>>(img, out);
}